// round 3
// baseline (speedup 1.0000x reference)
#include <cuda_runtime.h>

#define NN    8192
#define NT    512
#define EPB   16          // NT*EPB == NN
#define MAXO  300

// Scratch in __device__ globals (no allocation, no smem opt-in needed).
// Fully rewritten on every launch -> deterministic across graph replays.
__device__ unsigned long long g_keys[NN];   // (~score_bits << 32) | orig_idx
__device__ float4             g_boxes[NN];  // boxes in sorted (score-desc) order
__device__ int                g_sidx[NN];   // sorted pos -> original index

__global__ __launch_bounds__(NT, 1)
void nms_kernel(const float4* __restrict__ rois,
                const float*  __restrict__ scores,
                float* __restrict__ out) {
  __shared__ unsigned char sup8[NN];   // 8KB: 1 byte per sorted position
  __shared__ int cur_i;
  const int tid = threadIdx.x;

  // ---- build sort keys; zero suppression bytes; init output (float32!) ----
  for (int p = tid; p < NN; p += NT) {
    unsigned sb = __float_as_uint(scores[p]);   // scores >= 0 -> bits monotone
    g_keys[p] = (((unsigned long long)(~sb)) << 32) | (unsigned)p;
    sup8[p] = 0;
  }
  if (tid < MAXO) out[tid] = -1.0f;
  __syncthreads();

  // ---- bitonic sort ascending (== descending score, ties by ascending idx) ----
  for (unsigned k = 2; k <= NN; k <<= 1) {
    for (unsigned jj = k >> 1; jj; jj >>= 1) {
      for (unsigned t = tid; t < NN; t += NT) {
        unsigned ixj = t ^ jj;
        if (ixj > t) {
          unsigned long long a = g_keys[t];
          unsigned long long b = g_keys[ixj];
          if ((a > b) == ((t & k) == 0)) { g_keys[t] = b; g_keys[ixj] = a; }
        }
      }
      __syncthreads();
    }
  }

  // ---- gather sorted boxes into registers, precompute areas ----
  float4 bx[EPB];
  float  aj[EPB];
  const int base = tid * EPB;
#pragma unroll
  for (int e = 0; e < EPB; e++) {
    int p = base + e;
    int id = (int)(unsigned)(g_keys[p] & 0xFFFFFFFFull);
    g_sidx[p] = id;
    float4 bb = rois[id];
    g_boxes[p] = bb;
    bx[e] = bb;
    aj[e] = __fmul_rn(__fsub_rn(bb.z, bb.x), __fsub_rn(bb.w, bb.y));
  }
  __syncthreads();

  // ---- greedy NMS over kept rows only (<= MAXO iterations) ----
  unsigned mymask = 0;          // bit e set => position base+e suppressed
  int cursor = 0, outc = 0;     // meaningful in thread 0 only
  const unsigned* supw = reinterpret_cast<const unsigned*>(sup8);

  while (true) {
    if (tid == 0) {
      int found = -1;
      if (outc < MAXO) {
        unsigned c = (unsigned)cursor;
        while (c < NN) {
          unsigned w = supw[c >> 2];
          // bytes below the cursor inside this word count as suppressed
          unsigned off = (c & 3u) * 8u;
          unsigned zb = ~w & 0x01010101u & (0xFFFFFFFFu << off);
          if (zb) { c = (c & ~3u) + (unsigned)((__ffs(zb) - 1) >> 3); found = (int)c; break; }
          c = (c & ~3u) + 4u;
        }
      }
      cur_i = found;
      if (found >= 0) {
        out[outc++] = (float)g_sidx[found];   // float32 output!
        cursor = found + 1;
      }
    }
    __syncthreads();
    const int i = cur_i;
    if (i < 0) break;

    if (base + EPB - 1 > i && mymask != 0xFFFFu) {
      float4 bi = g_boxes[i];                 // same addr all lanes: broadcast
      float ai = __fmul_rn(__fsub_rn(bi.z, bi.x), __fsub_rn(bi.w, bi.y));
      unsigned m = mymask;
#pragma unroll
      for (int e = 0; e < EPB; e++) {
        int j = base + e;
        if (j > i && !((m >> e) & 1u)) {
          float lx = fmaxf(bi.x, bx[e].x);
          float ly = fmaxf(bi.y, bx[e].y);
          float rx = fminf(bi.z, bx[e].z);
          float ry = fminf(bi.w, bx[e].w);
          float w  = fmaxf(__fsub_rn(rx, lx), 0.0f);
          float h  = fmaxf(__fsub_rn(ry, ly), 0.0f);
          float inter = __fmul_rn(w, h);
          float uni   = __fsub_rn(__fadd_rn(ai, aj[e]), inter);
          // decide (inter/uni > 0.5) exactly: margin test, IEEE-divide fallback
          float d   = __fmaf_rn(-0.5f, uni, inter);
          float tol = 1e-6f * uni;
          bool sup;
          if (d > tol)        sup = true;
          else if (d < -tol)  sup = false;
          else                sup = (__fdiv_rn(inter, uni) > 0.5f);
          if (sup) { m |= (1u << e); sup8[j] = 1; }
        }
      }
      mymask = m;
    }
    __syncthreads();   // publish sup8 before thread 0's next scan
  }
}

extern "C" void kernel_launch(void* const* d_in, const int* in_sizes, int n_in,
                              void* d_out, int out_size) {
  // rois ([N,4]) is the larger input; scores is [N]
  const void* a0 = d_in[0];
  const void* a1 = d_in[1];
  const float4* rois;
  const float*  scores;
  if (in_sizes[0] >= in_sizes[1]) { rois = (const float4*)a0; scores = (const float*)a1; }
  else                            { rois = (const float4*)a1; scores = (const float*)a0; }

  nms_kernel<<<1, NT>>>(rois, scores, (float*)d_out);
}

// round 4
// speedup vs baseline: 1.4040x; 1.4040x over previous
#include <cuda_runtime.h>

#define NN    8192
#define NT    512
#define EPB   16          // NT*EPB == NN
#define MAXO  300
#define NW    (NN/64)     // 128 u64 words per mask row

// Static device scratch (no allocation). Fully rewritten every launch.
__device__ float4             g_boxes[NN];        // boxes in score-desc order
__device__ float              g_area[NN];         // areas in score-desc order
__device__ int                g_sidx[NN];         // sorted pos -> original idx
__device__ unsigned long long g_mask[(size_t)NN * NW];  // 8MB suppression matrix

// ---------------------------------------------------------------------------
// Kernel A: bitonic sort of (~score_bits<<32 | idx) keys, smem + registers.
// Blocked layout: thread t owns positions [t*16, t*16+16). All strides jj<=8
// are register-local; phases k<=16 are a pure register network.
// ---------------------------------------------------------------------------
__global__ __launch_bounds__(NT, 1)
void sort_kernel(const float4* __restrict__ rois,
                 const float*  __restrict__ scores,
                 float* __restrict__ out) {
  extern __shared__ unsigned long long sk[];   // 64KB
  const int tid = threadIdx.x;

  for (int p = tid; p < NN; p += NT) {
    unsigned sb = __float_as_uint(scores[p]);  // scores >= 0 -> bits monotone
    sk[p] = (((unsigned long long)(~sb)) << 32) | (unsigned)p;
  }
  if (tid < MAXO) out[tid] = -1.0f;            // float32 output, -1 padded
  __syncthreads();

  const int base = tid * EPB;
  unsigned long long v[EPB];
#pragma unroll
  for (int e = 0; e < EPB; e++) v[e] = sk[base + e];

  // phases k = 2..16: entirely in registers (directions vary inside block)
#pragma unroll
  for (int k = 2; k <= 16; k <<= 1) {
#pragma unroll
    for (int jj = k >> 1; jj > 0; jj >>= 1) {
#pragma unroll
      for (int e = 0; e < EPB; e++) {
        int e2 = e ^ jj;
        if (e2 > e) {
          bool up = (((base + e) & k) == 0);
          unsigned long long a = v[e], b = v[e2];
          if ((a > b) == up) { v[e] = b; v[e2] = a; }
        }
      }
    }
  }
#pragma unroll
  for (int e = 0; e < EPB; e++) sk[base + e] = v[e];
  __syncthreads();

  // phases k = 32..8192: shared passes for jj>=16, register passes for jj<=8
  for (int k = 32; k <= NN; k <<= 1) {
    for (int jj = k >> 1; jj >= 16; jj >>= 1) {
      for (int pp = tid; pp < NN / 2; pp += NT) {
        int p = ((pp & ~(jj - 1)) << 1) | (pp & (jj - 1));
        int q = p | jj;
        bool up = ((p & k) == 0);
        unsigned long long a = sk[p], b = sk[q];
        if ((a > b) == up) { sk[p] = b; sk[q] = a; }
      }
      __syncthreads();
    }
#pragma unroll
    for (int e = 0; e < EPB; e++) v[e] = sk[base + e];
    {
      bool up = ((base & k) == 0);   // uniform over the 16 local elements
#pragma unroll
      for (int jj = 8; jj > 0; jj >>= 1) {
#pragma unroll
        for (int e = 0; e < EPB; e++) {
          int e2 = e ^ jj;
          if (e2 > e) {
            unsigned long long a = v[e], b = v[e2];
            if ((a > b) == up) { v[e] = b; v[e2] = a; }
          }
        }
      }
    }
#pragma unroll
    for (int e = 0; e < EPB; e++) sk[base + e] = v[e];
    __syncthreads();
  }

  // emit sorted metadata (v still holds the final sorted block)
#pragma unroll
  for (int e = 0; e < EPB; e++) {
    int p = base + e;
    int id = (int)(unsigned)(v[e] & 0xFFFFFFFFull);
    g_sidx[p] = id;
    float4 bb = rois[id];
    g_boxes[p] = bb;
    g_area[p] = __fmul_rn(__fsub_rn(bb.z, bb.x), __fsub_rn(bb.w, bb.y));
  }
}

// ---------------------------------------------------------------------------
// Kernel B: full upper-triangular suppression bitmask. Block = one row i,
// thread w = 64-bit word w (columns j in [w*64, w*64+64)).
// ---------------------------------------------------------------------------
__global__ __launch_bounds__(NW, 8)
void mask_kernel() {
  const int i = blockIdx.x;
  const int w = threadIdx.x;
  unsigned long long* dst = &g_mask[(size_t)i * NW + w];
  const int j0 = w * 64;
  if (j0 + 64 <= i) { *dst = 0ull; return; }   // fully below diagonal

  const float4 bi = g_boxes[i];
  const float  ai = g_area[i];
  unsigned long long bits = 0;
#pragma unroll 4
  for (int e = 0; e < 64; e++) {
    int j = j0 + e;
    float4 bj = g_boxes[j];
    float lx = fmaxf(bi.x, bj.x);
    float ly = fmaxf(bi.y, bj.y);
    float rx = fminf(bi.z, bj.z);
    float ry = fminf(bi.w, bj.w);
    float ww = fmaxf(__fsub_rn(rx, lx), 0.0f);
    float hh = fmaxf(__fsub_rn(ry, ly), 0.0f);
    float inter = __fmul_rn(ww, hh);
    float uni   = __fsub_rn(__fadd_rn(ai, g_area[j]), inter);
    // decide (inter/uni > 0.5) exactly: margin test, IEEE-divide fallback
    float d   = __fmaf_rn(-0.5f, uni, inter);
    float tol = 1e-6f * uni;
    bool sup;
    if (d > tol)       sup = true;
    else if (d < -tol) sup = false;
    else               sup = (__fdiv_rn(inter, uni) > 0.5f);
    bits |= ((unsigned long long)sup) << e;
  }
  *dst = bits;
}

// ---------------------------------------------------------------------------
// Kernel C: single-warp greedy collect. removed[128 words] in registers
// (lane l owns words q*32+l); find-next via ffsll + shfl-min; OR row = 4
// coalesced LDG.64 per lane.
// ---------------------------------------------------------------------------
__global__ void greedy_kernel(float* __restrict__ out) {
  __shared__ int sidx_s[NN];                    // 32KB
  const int lane = threadIdx.x;
  for (int p = lane; p < NN; p += 32) sidx_s[p] = g_sidx[p];
  __syncwarp();

  unsigned long long rem[4] = {0ull, 0ull, 0ull, 0ull};
  int c = 0, outc = 0;

  while (outc < MAXO) {
    int best = NN;
#pragma unroll
    for (int q = 0; q < 4; q++) {
      int wi = q * 32 + lane;
      int bj = wi * 64;
      if (bj + 64 > c) {
        unsigned long long f = ~rem[q];
        if (bj < c) f &= (~0ull) << (c - bj);
        if (f) {
          int j = bj + (__ffsll((long long)f) - 1);
          if (j < best) best = j;
        }
      }
    }
#pragma unroll
    for (int off = 16; off; off >>= 1) {
      int o = __shfl_xor_sync(0xFFFFFFFFu, best, off);
      best = min(best, o);
    }
    if (best >= NN) break;

    if (lane == 0) out[outc] = (float)sidx_s[best];
    outc++;

    const unsigned long long* row = &g_mask[(size_t)best * NW];
#pragma unroll
    for (int q = 0; q < 4; q++) rem[q] |= row[q * 32 + lane];
    c = best + 1;
  }
}

// ---------------------------------------------------------------------------
extern "C" void kernel_launch(void* const* d_in, const int* in_sizes, int n_in,
                              void* d_out, int out_size) {
  const void* a0 = d_in[0];
  const void* a1 = d_in[1];
  const float4* rois;
  const float*  scores;
  if (in_sizes[0] >= in_sizes[1]) { rois = (const float4*)a0; scores = (const float*)a1; }
  else                            { rois = (const float4*)a1; scores = (const float*)a0; }

  cudaFuncSetAttribute(sort_kernel, cudaFuncAttributeMaxDynamicSharedMemorySize,
                       NN * (int)sizeof(unsigned long long));
  sort_kernel<<<1, NT, NN * sizeof(unsigned long long)>>>(rois, scores, (float*)d_out);
  mask_kernel<<<NN, NW>>>();
  greedy_kernel<<<1, 32>>>((float*)d_out);
}

// round 5
// speedup vs baseline: 2.9161x; 2.0770x over previous
#include <cuda_runtime.h>

#define NN    8192
#define NT    512
#define EPB   16          // NT*EPB == NN
#define MAXO  300
#define NW    (NN/64)     // 128 u64 words per mask row

typedef unsigned long long u64;

// Static device scratch (no allocation). Fully rewritten every launch.
__device__ float4 g_boxes[NN];
__device__ float  g_area[NN];
__device__ int    g_sidx[NN];
__device__ __align__(16) u64 g_mask[(size_t)NN * NW];   // 8MB, self+above-diag bits

__device__ __forceinline__ void cmpex(u64& a, u64& b, bool up) {
  u64 x = a, y = b;
  if ((x > y) == up) { a = y; b = x; }
}

// ---------------------------------------------------------------------------
// Kernel A: bitonic sort of (~score_bits<<32 | idx). Blocked registers:
// thread t owns elements [t*16, t*16+16). jj<=8: register passes.
// jj in [16,256]: shfl_xor passes (no barriers). jj>=512: smem passes.
// ---------------------------------------------------------------------------
__global__ __launch_bounds__(NT, 1)
void sort_kernel(const float4* __restrict__ rois,
                 const float*  __restrict__ scores,
                 float* __restrict__ out) {
  extern __shared__ u64 sk[];   // 64KB
  const int tid  = threadIdx.x;
  const int base = tid * EPB;

  for (int p = tid; p < NN; p += NT) {
    unsigned sb = __float_as_uint(scores[p]);  // scores >= 0 -> bits monotone
    sk[p] = (((u64)(~sb)) << 32) | (unsigned)p;
  }
  if (tid < MAXO) out[tid] = -1.0f;
  __syncthreads();

  u64 v[EPB];
#pragma unroll
  for (int e = 0; e < EPB; e++) v[e] = sk[base + e];

  // ---- k = 2,4,8: direction varies with e only ----
#pragma unroll
  for (int k = 2; k <= 8; k <<= 1) {
#pragma unroll
    for (int jj = k >> 1; jj; jj >>= 1) {
#pragma unroll
      for (int e = 0; e < EPB; e++) {
        int e2 = e ^ jj;
        if (e2 > e) cmpex(v[e], v[e2], ((e & k) == 0));
      }
    }
  }
  // ---- k = 16: direction uniform per thread ----
  {
    bool up = ((base & 16) == 0);
#pragma unroll
    for (int jj = 8; jj; jj >>= 1)
#pragma unroll
      for (int e = 0; e < EPB; e++) {
        int e2 = e ^ jj;
        if (e2 > e) cmpex(v[e], v[e2], up);
      }
  }

  // ---- k = 32 .. 8192 ----
  for (int k = 32; k <= NN; k <<= 1) {
    int jj = k >> 1;
    if (jj >= 512) {                       // cross-warp strides: smem passes
#pragma unroll
      for (int e = 0; e < EPB; e++) sk[base + e] = v[e];
      __syncthreads();
      for (; jj >= 512; jj >>= 1) {
        for (int pp = tid; pp < NN / 2; pp += NT) {
          int p = ((pp & ~(jj - 1)) << 1) | (pp & (jj - 1));
          int q = p | jj;
          bool up = ((p & k) == 0);
          u64 a = sk[p], b = sk[q];
          if ((a > b) == up) { sk[p] = b; sk[q] = a; }
        }
        __syncthreads();
      }
#pragma unroll
      for (int e = 0; e < EPB; e++) v[e] = sk[base + e];
    }
    const bool up = ((base & k) == 0);     // uniform per thread for k >= 32
    // shfl passes: jj = 256..16 (thread stride s = jj/16 in [1,16])
    for (; jj >= 16; jj >>= 1) {
      int s = jj >> 4;
      bool takemin = (((tid & s) == 0) == up);
#pragma unroll
      for (int e = 0; e < EPB; e++) {
        u64 o  = __shfl_xor_sync(0xFFFFFFFFu, v[e], s);
        u64 mn = (v[e] < o) ? v[e] : o;
        u64 mx = (v[e] < o) ? o : v[e];
        v[e] = takemin ? mn : mx;
      }
    }
    // register passes: jj = 8..1
#pragma unroll
    for (int j2 = 8; j2; j2 >>= 1)
#pragma unroll
      for (int e = 0; e < EPB; e++) {
        int e2 = e ^ j2;
        if (e2 > e) cmpex(v[e], v[e2], up);
      }
  }

  // ---- emit sorted metadata ----
#pragma unroll
  for (int e = 0; e < EPB; e++) {
    int p  = base + e;
    int id = (int)(unsigned)(v[e] & 0xFFFFFFFFull);
    g_sidx[p] = id;
    float4 bb = rois[id];
    g_boxes[p] = bb;
    g_area[p] = __fmul_rn(__fsub_rn(bb.z, bb.x), __fsub_rn(bb.w, bb.y));
  }
}

// ---------------------------------------------------------------------------
// Kernel B: suppression bitmask, 64x64 tiles (torchvision layout).
// Block (cb, rb): 64 threads; thread t = row i = rb*64+t, word cb of row i.
// Column boxes staged in smem (coalesced load, broadcast reads).
// Bit e set  <=>  j = cb*64+e satisfies j >= i AND IoU(i,j) > 0.5.
// (diagonal bit is set: IoU(i,i)=1 — used by greedy to mark selections)
// ---------------------------------------------------------------------------
__global__ __launch_bounds__(64, 16)
void mask_kernel() {
  const int cb = blockIdx.x, rb = blockIdx.y;
  const int t = threadIdx.x;
  const int i = rb * 64 + t;
  if (cb < rb) { g_mask[(size_t)i * NW + cb] = 0ull; return; }

  __shared__ float4 cbox[64];
  __shared__ float  carea[64];
  cbox[t]  = g_boxes[cb * 64 + t];
  carea[t] = g_area[cb * 64 + t];
  __syncthreads();

  const float4 bi = g_boxes[i];
  const float  ai = g_area[i];
  u64 bits = 0;
#pragma unroll 4
  for (int e = 0; e < 64; e++) {
    float4 bj = cbox[e];
    float lx = fmaxf(bi.x, bj.x);
    float ly = fmaxf(bi.y, bj.y);
    float rx = fminf(bi.z, bj.z);
    float ry = fminf(bi.w, bj.w);
    float ww = fmaxf(__fsub_rn(rx, lx), 0.0f);
    float hh = fmaxf(__fsub_rn(ry, ly), 0.0f);
    float inter = __fmul_rn(ww, hh);
    float uni   = __fsub_rn(__fadd_rn(ai, carea[e]), inter);
    // decide (inter/uni > 0.5) exactly: margin test, IEEE-divide fallback
    float d   = __fmaf_rn(-0.5f, uni, inter);
    float tol = 1e-6f * uni;
    bool sup;
    if (d > tol)       sup = true;
    else if (d < -tol) sup = false;
    else               sup = (__fdiv_rn(inter, uni) > 0.5f);
    bits |= ((u64)sup) << e;
  }
  if (cb == rb) bits &= (~0ull) << t;      // keep only j >= i
  g_mask[(size_t)i * NW + cb] = bits;
}

// ---------------------------------------------------------------------------
// Kernel C: single-warp greedy. Lane l owns j in [256l, 256l+256) as 4 u64.
// find-next = per-lane ffsll + ballot + shfl. Row OR marks the selection
// itself via the diagonal bit, so no cursor is needed.
// ---------------------------------------------------------------------------
__global__ void greedy_kernel(float* __restrict__ out) {
  const int lane = threadIdx.x;
  ulonglong2 r01 = make_ulonglong2(0ull, 0ull);
  ulonglong2 r23 = make_ulonglong2(0ull, 0ull);
  int outc = 0;

  while (outc < MAXO) {
    int cand = NN;
    u64 f;
    if ((f = ~r01.x))      cand = 256 * lane +       (__ffsll((long long)f) - 1);
    else if ((f = ~r01.y)) cand = 256 * lane +  64 + (__ffsll((long long)f) - 1);
    else if ((f = ~r23.x)) cand = 256 * lane + 128 + (__ffsll((long long)f) - 1);
    else if ((f = ~r23.y)) cand = 256 * lane + 192 + (__ffsll((long long)f) - 1);

    unsigned bal = __ballot_sync(0xFFFFFFFFu, cand < NN);
    if (!bal) break;
    int src  = __ffs(bal) - 1;               // lowest lane == lowest j
    int best = __shfl_sync(0xFFFFFFFFu, cand, src);

    if (lane == 0) out[outc] = (float)g_sidx[best];
    outc++;

    const ulonglong2* row =
        reinterpret_cast<const ulonglong2*>(&g_mask[(size_t)best * NW]);
    ulonglong2 a = row[2 * lane];             // words 4l, 4l+1
    ulonglong2 b = row[2 * lane + 1];         // words 4l+2, 4l+3
    r01.x |= a.x; r01.y |= a.y;
    r23.x |= b.x; r23.y |= b.y;
  }
}

// ---------------------------------------------------------------------------
extern "C" void kernel_launch(void* const* d_in, const int* in_sizes, int n_in,
                              void* d_out, int out_size) {
  const void* a0 = d_in[0];
  const void* a1 = d_in[1];
  const float4* rois;
  const float*  scores;
  if (in_sizes[0] >= in_sizes[1]) { rois = (const float4*)a0; scores = (const float*)a1; }
  else                            { rois = (const float4*)a1; scores = (const float*)a0; }

  cudaFuncSetAttribute(sort_kernel, cudaFuncAttributeMaxDynamicSharedMemorySize,
                       NN * (int)sizeof(u64));
  sort_kernel<<<1, NT, NN * sizeof(u64)>>>(rois, scores, (float*)d_out);
  mask_kernel<<<dim3(NW, NN / 64), 64>>>();
  greedy_kernel<<<1, 32>>>((float*)d_out);
}